// round 14
// baseline (speedup 1.0000x reference)
#include <cuda_runtime.h>
#include <cuda_fp16.h>
#include <math.h>

#define ASTRIDE 160
#define AWARP   (32 * ASTRIDE)          // 5120 B per warp
#define AREG    (8 * AWARP)             // 40960
#define BREG    (256 * ASTRIDE)         // 40960
#define SMTOT   (AREG + BREG + 64)

typedef unsigned int u32;

extern __shared__ char dynsm[];

#define MMA(D, a0, a1, a2, a3, b0, b1) asm volatile( \
    "mma.sync.aligned.m16n8k16.row.col.f32.f16.f16.f32 " \
    "{%0,%1,%2,%3},{%4,%5,%6,%7},{%8,%9},{%0,%1,%2,%3};" \
    : "+f"((D)[0]), "+f"((D)[1]), "+f"((D)[2]), "+f"((D)[3]) \
    : "r"(a0), "r"(a1), "r"(a2), "r"(a3), "r"(b0), "r"(b1))

__global__ __launch_bounds__(256, 1)
void gmm_mma(const float4* __restrict__ samples4,
             const float* __restrict__ Phi,
             const float* __restrict__ mu,
             const float* __restrict__ Sigma,
             float* __restrict__ out, int N) {
    char*  smA = dynsm;
    char*  smB = dynsm + AREG;
    float* sC  = (float*)(dynsm + AREG + BREG);

    const int tid = threadIdx.x, wid = tid >> 5, lane = tid & 31;
    const int g = lane >> 2, t = lane & 3;

    // Zero B region (padding columns must be 0).
    for (int i = tid; i < BREG / 4; i += 256) ((u32*)smB)[i] = 0;

    // ---- Prologue: Cholesky + L^{-1} per mixture (scratch overlays smA) ----
    float* sL  = (float*)smA;            // [16] x [16][17]
    float* sMi = sL + 16 * 272;
    const int k2 = wid * 2 + (lane >> 4);
    const int r  = lane & 15;
    float mrow[16], v = 0.f, cnorm = 0.f;
    {
        float* L  = sL  + k2 * 272;
        float* Mi = sMi + k2 * 272;
        for (int j = 0; j < 16; j++) L[r * 17 + j] = Sigma[(k2 * 16 + r) * 16 + j];
        __syncwarp();
        for (int p = 0; p < 16; p++) {
            if (r == p) {
                float s = L[p * 17 + p];
                for (int q = 0; q < p; q++) s -= L[p * 17 + q] * L[p * 17 + q];
                L[p * 17 + p] = sqrtf(s);
            }
            __syncwarp();
            if (r > p) {
                float s = L[r * 17 + p];
                for (int q = 0; q < p; q++) s -= L[r * 17 + q] * L[p * 17 + q];
                L[r * 17 + p] = s / L[p * 17 + p];
            }
            __syncwarp();
        }
        {   // Mi = L^{-1}, lane r computes column r
            int c = r;
            for (int i = 0; i < c; i++) Mi[i * 17 + c] = 0.f;
            Mi[c * 17 + c] = 1.f / L[c * 17 + c];
            for (int i = c + 1; i < 16; i++) {
                float s = 0.f;
                for (int q = c; q < i; q++) s += L[i * 17 + q] * Mi[q * 17 + c];
                Mi[i * 17 + c] = -s / L[i * 17 + i];
            }
        }
        __syncwarp();
        for (int j = 0; j < 16; j++) mrow[j] = (j <= r) ? Mi[r * 17 + j] : 0.f;
        for (int j = 0; j <= r; j++) v += mrow[j] * mu[k2 * 16 + j];
        float prodL = 1.f;
        for (int i = 0; i < 16; i++) prodL *= L[i * 17 + i];
        cnorm = Phi[k2] / (sqrtf(2.f * 3.14159265358979323846f) * prodL);
    }
    __syncthreads();

    // ---- Build B row n = 16*k2 + r from registers ----
    // K layout: [Mhi(0:16), -vhi(16), 0 | Mhi(18:34), -vlo(34), 0 | Mlo(36:52) | 0..]
    {
        char* br = smB + (k2 * 16 + r) * ASTRIDE;
        for (int j = 0; j < 16; j++) {
            __half h = __float2half_rn(mrow[j]);
            __half l = __float2half_rn(mrow[j] - __half2float(h));
            *(__half*)(br + 2 * j)        = h;
            *(__half*)(br + 2 * (18 + j)) = h;
            *(__half*)(br + 2 * (36 + j)) = l;
        }
        __half vh = __float2half_rn(v);
        __half vl = __float2half_rn(v - __half2float(vh));
        *(__half*)(br + 2 * 16) = __hneg(vh);
        *(__half*)(br + 2 * 34) = __hneg(vl);
        if (r == 0) sC[k2] = cnorm;
    }

    // ---- Init own A row: zeros + constant 1.0 at k=16 and k=34 ----
    {
        char* ar = smA + wid * AWARP + lane * ASTRIDE;
        for (int j = 0; j < 40; j++) ((u32*)ar)[j] = 0;
        *(__half*)(ar + 2 * 16) = __float2half_rn(1.f);
        *(__half*)(ar + 2 * 34) = __float2half_rn(1.f);
    }
    __syncthreads();

    // ---- Main loop: 32 samples per warp-tile ----
    const int tiles = (N + 31) >> 5;
    for (int tt = blockIdx.x * 8 + wid; tt < tiles; tt += gridDim.x * 8) {
        long s0 = (long)tt << 5;
        {   // stage sample s0+lane: A = [xhi(0:16),1 | xlo(18:34),1 | xhi(36:52)]
            long sl = s0 + lane; if (sl > N - 1) sl = N - 1;
            const float4* sp = samples4 + sl * 4;
            float4 q0 = sp[0], q1 = sp[1], q2 = sp[2], q3 = sp[3];
            float x[16] = {q0.x,q0.y,q0.z,q0.w, q1.x,q1.y,q1.z,q1.w,
                           q2.x,q2.y,q2.z,q2.w, q3.x,q3.y,q3.z,q3.w};
            char* ar = smA + wid * AWARP + lane * ASTRIDE;
            #pragma unroll
            for (int j = 0; j < 8; j++) {
                __half2 h2 = __floats2half2_rn(x[2*j], x[2*j+1]);
                float2  hf = __half22float2(h2);
                __half2 l2 = __floats2half2_rn(x[2*j] - hf.x, x[2*j+1] - hf.y);
                *(__half2*)(ar + 4 * j)      = h2;   // k = 2j
                *(__half2*)(ar + 72 + 4 * j) = h2;   // k = 36+2j
                *(__half2*)(ar + 36 + 4 * j) = l2;   // k = 18+2j
            }
        }
        __syncwarp();

        #pragma unroll
        for (int T = 0; T < 2; T++) {
            float p0 = 0.f, p1 = 0.f;
            #pragma unroll
            for (int h = 0; h < 2; h++) {
                float D[16][4];
                #pragma unroll
                for (int m = 0; m < 16; m++)
                    D[m][0] = D[m][1] = D[m][2] = D[m][3] = 0.f;
                #pragma unroll
                for (int c = 0; c < 4; c++) {
                    const char* ap = smA + wid * AWARP
                                   + (T * 16 + g) * ASTRIDE + c * 32 + t * 4;
                    u32 a0 = *(const u32*)ap;
                    u32 a1 = *(const u32*)(ap + 8 * ASTRIDE);
                    u32 a2 = *(const u32*)(ap + 16);
                    u32 a3 = *(const u32*)(ap + 8 * ASTRIDE + 16);
                    #pragma unroll
                    for (int m = 0; m < 16; m++) {
                        const char* bp = smB + (h * 128 + m * 8 + g) * ASTRIDE
                                       + c * 32 + t * 4;
                        u32 b0 = *(const u32*)bp;
                        u32 b1 = *(const u32*)(bp + 16);
                        MMA(D[m], a0, a1, a2, a3, b0, b1);
                    }
                }
                // epilogue: mixture km holds frags 2km, 2km+1
                #pragma unroll
                for (int km = 0; km < 8; km++) {
                    float q0 = D[2*km][0]*D[2*km][0] + D[2*km][1]*D[2*km][1]
                             + D[2*km+1][0]*D[2*km+1][0] + D[2*km+1][1]*D[2*km+1][1];
                    float q1 = D[2*km][2]*D[2*km][2] + D[2*km][3]*D[2*km][3]
                             + D[2*km+1][2]*D[2*km+1][2] + D[2*km+1][3]*D[2*km+1][3];
                    q0 += __shfl_xor_sync(0xffffffffu, q0, 1);
                    q0 += __shfl_xor_sync(0xffffffffu, q0, 2);
                    q1 += __shfl_xor_sync(0xffffffffu, q1, 1);
                    q1 += __shfl_xor_sync(0xffffffffu, q1, 2);
                    float ck = sC[h * 8 + km];
                    p0 += ck * __expf(-0.5f * q0);
                    p1 += ck * __expf(-0.5f * q1);
                }
            }
            if (t == 0) {
                long so = s0 + T * 16 + g;
                if (so < N)     out[so]     = -__logf(p0);
                if (so + 8 < N) out[so + 8] = -__logf(p1);
            }
        }
    }
}

// ---------------------------------------------------------------------------
extern "C" void kernel_launch(void* const* d_in, const int* in_sizes, int n_in,
                              void* d_out, int out_size) {
    const float* samples = (const float*)d_in[0];
    const float* Phi     = (const float*)d_in[1];
    const float* mu      = (const float*)d_in[2];
    const float* Sigma   = (const float*)d_in[3];
    int N = in_sizes[0] / 16;

    cudaFuncSetAttribute(gmm_mma, cudaFuncAttributeMaxDynamicSharedMemorySize,
                         SMTOT);
    gmm_mma<<<148, 256, SMTOT>>>((const float4*)samples, Phi, mu, Sigma,
                                 (float*)d_out, N);
}